// round 13
// baseline (speedup 1.0000x reference)
#include <cuda_runtime.h>
#include <cstdint>

// Problem constants
#define T_  40
#define H_  40
#define G_  160   // 4*H
#define C_  4
#define BLK 128
#define SPB 256   // sequences per block (2 per thread)

typedef unsigned long long ull;

// HW tanh (MUFU.TANH)
__device__ __forceinline__ float tanh_hw(float x) {
    float r; asm("tanh.approx.f32 %0, %1;" : "=f"(r) : "f"(x)); return r;
}
__device__ __forceinline__ float fsigm(float x) {
    return fmaf(0.5f, tanh_hw(0.5f * x), 0.5f);
}

// packed f32x2 helpers
__device__ __forceinline__ ull pk2(float lo, float hi) {
    ull r; asm("mov.b64 %0, {%1, %2};" : "=l"(r) : "f"(lo), "f"(hi)); return r;
}
__device__ __forceinline__ void upk2(float& lo, float& hi, ull v) {
    asm("mov.b64 {%0, %1}, %2;" : "=f"(lo), "=f"(hi) : "l"(v));
}
__device__ __forceinline__ void ffma2(ull& d, ull a, ull b) {
    asm("fma.rn.f32x2 %0, %1, %2, %0;" : "+l"(d) : "l"(a), "l"(b));
}

extern __shared__ float smem[];

// Shared layout (weights only — 28.8 KB so 4 CTAs/SM fit):
//   sW    [160*40] = 6400           @0
//   sWfc  [4*40]=160                @6400
//   sbfc  [8]                       @6560
//   -- 16B-aligned ull region @6568 --
//   sWP  ull[160]  (w_in, 0) packed, index [u*4+gate]
//   sBP  ull[160]  (b, 0)   packed, index [u*4+gate]
#define OFF_WFC 6400
#define OFF_BFC 6560
#define OFF_ULL 6568
#define SMEM_BYTES (OFF_ULL * 4 + (2 * G_) * 8)   // 28832 B

__global__ __launch_bounds__(BLK, 4)
void lstm_fused_kernel(const float* __restrict__ x,
                       const float* __restrict__ W_ih,
                       const float* __restrict__ W_hh,
                       const float* __restrict__ b_ih,
                       const float* __restrict__ b_hh,
                       const float* __restrict__ W_fc,
                       const float* __restrict__ b_fc,
                       float* __restrict__ out,
                       long long logit_off,
                       long long arg_off)
{
    float* sW   = smem;
    float* sWfc = smem + OFF_WFC;
    float* sbfc = smem + OFF_BFC;
    ull*   sWP  = (ull*)(smem + OFF_ULL);
    ull*   sBP  = sWP + G_;

    const int tid = threadIdx.x;

    // Stage weights
    for (int i = tid; i < G_ * H_; i += BLK) sW[i] = W_hh[i];
    for (int i = tid; i < G_; i += BLK) {
        const int g = i / H_, u = i % H_;
        sWP[u * 4 + g] = pk2(W_ih[i], 0.0f);
        sBP[u * 4 + g] = pk2(b_ih[i] + b_hh[i], 0.0f);
    }
    for (int i = tid; i < C_ * H_; i += BLK) sWfc[i] = W_fc[i];
    if (tid < C_) sbfc[tid] = b_fc[tid];
    __syncthreads();

    const long long seqA = (long long)blockIdx.x * SPB + tid;
    const long long seqB = seqA + BLK;
    const float* xA_ptr = x + seqA * T_;
    const float* xB_ptr = x + seqB * T_;

    // h pairs in registers; cell state + h_new staging in per-thread LOCAL
    ull hA[20], hB[20];
    ull cL[40];             // (cA,cB) packed per unit
    ull hLA[20], hLB[20];   // h_new staging ring
#pragma unroll
    for (int j = 0; j < 20; j++) { hA[j] = 0ULL; hB[j] = 0ULL; }
#pragma unroll
    for (int j = 0; j < 40; j++) cL[j] = 0ULL;

    float xA = xA_ptr[0];
    float xB = xB_ptr[0];
    float hnAp = 0.0f, hnBp = 0.0f;

#pragma unroll 1
    for (int t = 0; t < T_; t++) {
        float xAn = 0.0f, xBn = 0.0f;
        if (t + 1 < T_) { xAn = xA_ptr[t + 1]; xBn = xB_ptr[t + 1]; }

        const ull xx2A = pk2(xA, xA);
        const ull xx2B = pk2(xB, xB);

#pragma unroll 2
        for (int u = 0; u < H_; u++) {
            // ---- pass 1: gates i, f (both seqs) ----
            float vAi, vAf, vBi, vBf;
            {
                const ulonglong2 bp = *(const ulonglong2*)(sBP + u * 4);
                const ulonglong2 wp = *(const ulonglong2*)(sWP + u * 4);
                ull aAi = bp.x, aAf = bp.y, aBi = bp.x, aBf = bp.y;
                ffma2(aAi, wp.x, xx2A); ffma2(aAf, wp.y, xx2A);
                ffma2(aBi, wp.x, xx2B); ffma2(aBf, wp.y, xx2B);

                const ulonglong2* Wi = (const ulonglong2*)(sW + u * H_);
                const ulonglong2* Wf = (const ulonglong2*)(sW + (H_ + u) * H_);
#pragma unroll
                for (int c = 0; c < 10; c++) {
                    ulonglong2 vi = Wi[c];
                    ulonglong2 vf = Wf[c];
                    ffma2(aAi, vi.x, hA[2*c]); ffma2(aAi, vi.y, hA[2*c+1]);
                    ffma2(aBi, vi.x, hB[2*c]); ffma2(aBi, vi.y, hB[2*c+1]);
                    ffma2(aAf, vf.x, hA[2*c]); ffma2(aAf, vf.y, hA[2*c+1]);
                    ffma2(aBf, vf.x, hB[2*c]); ffma2(aBf, vf.y, hB[2*c+1]);
                }
                float lo, hi;
                upk2(lo, hi, aAi); vAi = lo + hi;
                upk2(lo, hi, aAf); vAf = lo + hi;
                upk2(lo, hi, aBi); vBi = lo + hi;
                upk2(lo, hi, aBf); vBf = lo + hi;
            }

            // ---- pass 2: gates g, o (both seqs) ----
            float vAg, vAo, vBg, vBo;
            {
                const ulonglong2 bp = *(const ulonglong2*)(sBP + u * 4 + 2);
                const ulonglong2 wp = *(const ulonglong2*)(sWP + u * 4 + 2);
                ull aAg = bp.x, aAo = bp.y, aBg = bp.x, aBo = bp.y;
                ffma2(aAg, wp.x, xx2A); ffma2(aAo, wp.y, xx2A);
                ffma2(aBg, wp.x, xx2B); ffma2(aBo, wp.y, xx2B);

                const ulonglong2* Wg = (const ulonglong2*)(sW + (2*H_ + u) * H_);
                const ulonglong2* Wo = (const ulonglong2*)(sW + (3*H_ + u) * H_);
#pragma unroll
                for (int c = 0; c < 10; c++) {
                    ulonglong2 vg = Wg[c];
                    ulonglong2 vo = Wo[c];
                    ffma2(aAg, vg.x, hA[2*c]); ffma2(aAg, vg.y, hA[2*c+1]);
                    ffma2(aBg, vg.x, hB[2*c]); ffma2(aBg, vg.y, hB[2*c+1]);
                    ffma2(aAo, vo.x, hA[2*c]); ffma2(aAo, vo.y, hA[2*c+1]);
                    ffma2(aBo, vo.x, hB[2*c]); ffma2(aBo, vo.y, hB[2*c+1]);
                }
                float lo, hi;
                upk2(lo, hi, aAg); vAg = lo + hi;
                upk2(lo, hi, aAo); vAo = lo + hi;
                upk2(lo, hi, aBg); vBg = lo + hi;
                upk2(lo, hi, aBo); vBo = lo + hi;
            }

            const float iA = fsigm(vAi), fA = fsigm(vAf), gA = tanh_hw(vAg), oA = fsigm(vAo);
            const float iB = fsigm(vBi), fB = fsigm(vBf), gB = tanh_hw(vBg), oB = fsigm(vBo);

            float cA, cB;
            upk2(cA, cB, cL[u]);
            const float cnA = fmaf(fA, cA, iA * gA);
            const float cnB = fmaf(fB, cB, iB * gB);
            cL[u] = pk2(cnA, cnB);
            const float hnA = oA * tanh_hw(cnA);
            const float hnB = oB * tanh_hw(cnB);

            if (u & 1) {
                hLA[u >> 1] = pk2(hnAp, hnA);
                hLB[u >> 1] = pk2(hnBp, hnB);
            } else {
                hnAp = hnA; hnBp = hnB;
            }
        }

        // commit h_new -> packed h regs (bulk local reload, MLP=20)
#pragma unroll
        for (int j = 0; j < 20; j++) {
            hA[j] = hLA[j];
            hB[j] = hLB[j];
        }
        xA = xAn; xB = xBn;
    }

    // FC head (packed dot products)
    float lgA[C_], lgB[C_];
#pragma unroll
    for (int cc = 0; cc < C_; cc++) {
        const ulonglong2* W = (const ulonglong2*)(sWfc + cc * H_);
        ull aA = 0ULL, aB = 0ULL;
#pragma unroll
        for (int c = 0; c < 10; c++) {
            ulonglong2 w = W[c];
            ffma2(aA, w.x, hA[2*c]); ffma2(aA, w.y, hA[2*c+1]);
            ffma2(aB, w.x, hB[2*c]); ffma2(aB, w.y, hB[2*c+1]);
        }
        float lo, hi;
        upk2(lo, hi, aA); lgA[cc] = sbfc[cc] + lo + hi;
        upk2(lo, hi, aB); lgB[cc] = sbfc[cc] + lo + hi;
    }

    int bestA = 0, bestB = 0;
    float bvA = lgA[0], bvB = lgB[0];
#pragma unroll
    for (int cc = 1; cc < C_; cc++) {
        if (lgA[cc] > bvA) { bvA = lgA[cc]; bestA = cc; }
        if (lgB[cc] > bvB) { bvB = lgB[cc]; bestB = cc; }
    }

    if (logit_off >= 0) {
        *(float4*)(out + logit_off + seqA * 4) = make_float4(lgA[0], lgA[1], lgA[2], lgA[3]);
        *(float4*)(out + logit_off + seqB * 4) = make_float4(lgB[0], lgB[1], lgB[2], lgB[3]);
    }
    if (arg_off >= 0) {
        out[arg_off + seqA] = (float)bestA;
        out[arg_off + seqB] = (float)bestB;
    }
}

extern "C" void kernel_launch(void* const* d_in, const int* in_sizes, int n_in,
                              void* d_out, int out_size)
{
    const float* x    = (const float*)d_in[0];
    const float* W_ih = (const float*)d_in[1];
    const float* W_hh = (const float*)d_in[2];
    const float* b_ih = (const float*)d_in[3];
    const float* b_hh = (const float*)d_in[4];
    const float* W_fc = (const float*)d_in[5];
    const float* b_fc = (const float*)d_in[6];
    float* out = (float*)d_out;

    const long long Btot = in_sizes[0] / T_;

    long long logit_off = 0, arg_off = 4LL * Btot;   // default: both
    if (out_size == (int)(Btot * 5)) {
        logit_off = 0; arg_off = 4LL * Btot;
    } else if (out_size == (int)(Btot * 4)) {
        logit_off = 0; arg_off = -1;
    } else if (out_size == (int)Btot) {
        logit_off = -1; arg_off = 0;
    }

    cudaFuncSetAttribute(lstm_fused_kernel,
                         cudaFuncAttributeMaxDynamicSharedMemorySize,
                         (int)SMEM_BYTES);

    const int grid = (int)((Btot + SPB - 1) / SPB);
    lstm_fused_kernel<<<grid, BLK, SMEM_BYTES>>>(
        x, W_ih, W_hh, b_ih, b_hh, W_fc, b_fc, out, logit_off, arg_off);
}

// round 14
// speedup vs baseline: 1.0873x; 1.0873x over previous
#include <cuda_runtime.h>
#include <cstdint>

// Problem constants
#define T_  40
#define H_  40
#define G_  160   // 4*H
#define C_  4
#define BLK 128
#define SPB 256   // sequences per block (2 per thread)

typedef unsigned long long ull;

// HW tanh (MUFU.TANH)
__device__ __forceinline__ float tanh_hw(float x) {
    float r; asm("tanh.approx.f32 %0, %1;" : "=f"(r) : "f"(x)); return r;
}
__device__ __forceinline__ float fsigm(float x) {
    return fmaf(0.5f, tanh_hw(0.5f * x), 0.5f);
}

// packed f32x2 helpers
__device__ __forceinline__ ull pk2(float lo, float hi) {
    ull r; asm("mov.b64 %0, {%1, %2};" : "=l"(r) : "f"(lo), "f"(hi)); return r;
}
__device__ __forceinline__ void upk2(float& lo, float& hi, ull v) {
    asm("mov.b64 {%0, %1}, %2;" : "=f"(lo), "=f"(hi) : "l"(v));
}
__device__ __forceinline__ void ffma2(ull& d, ull a, ull b) {
    asm("fma.rn.f32x2 %0, %1, %2, %0;" : "+l"(d) : "l"(a), "l"(b));
}

extern __shared__ float smem[];

// Shared layout (float offsets):
//   sW    [160*40] = 6400           @0
//   sWfc  [4*40]=160                @6400
//   sbfc  [8]                       @6560
//   -- 16B-aligned ull region @6568 (byte 26272) --
//   sWP  ull[160]  (w_in, 0) packed, index [u*4+gate]
//   sBP  ull[160]  (b, 0)   packed, index [u*4+gate]
//   sC   ull[40*128]  (cA,cB packed per unit per thread)
#define OFF_WFC 6400
#define OFF_BFC 6560
#define OFF_ULL 6568
#define N_C   (H_ * BLK)       // 5120 ull
#define SMEM_BYTES (OFF_ULL * 4 + (2 * G_ + N_C) * 8)   // 69792 B -> 3 CTAs/SM

__global__ __launch_bounds__(BLK, 3)
void lstm_fused_kernel(const float* __restrict__ x,
                       const float* __restrict__ W_ih,
                       const float* __restrict__ W_hh,
                       const float* __restrict__ b_ih,
                       const float* __restrict__ b_hh,
                       const float* __restrict__ W_fc,
                       const float* __restrict__ b_fc,
                       float* __restrict__ out,
                       long long logit_off,
                       long long arg_off)
{
    float* sW   = smem;
    float* sWfc = smem + OFF_WFC;
    float* sbfc = smem + OFF_BFC;
    ull*   sWP  = (ull*)(smem + OFF_ULL);
    ull*   sBP  = sWP + G_;
    ull*   sC   = sBP + G_;

    const int tid = threadIdx.x;

    // Stage weights
    for (int i = tid; i < G_ * H_; i += BLK) sW[i] = W_hh[i];
    for (int i = tid; i < G_; i += BLK) {
        const int g = i / H_, u = i % H_;
        sWP[u * 4 + g] = pk2(W_ih[i], 0.0f);
        sBP[u * 4 + g] = pk2(b_ih[i] + b_hh[i], 0.0f);
    }
    for (int i = tid; i < C_ * H_; i += BLK) sWfc[i] = W_fc[i];
    if (tid < C_) sbfc[tid] = b_fc[tid];
    for (int i = tid; i < N_C; i += BLK) sC[i] = 0ULL;
    __syncthreads();

    const long long seqA = (long long)blockIdx.x * SPB + tid;
    const long long seqB = seqA + BLK;
    const float* xA_ptr = x + seqA * T_;
    const float* xB_ptr = x + seqB * T_;

    // h pairs in registers; h_new staged via per-thread LOCAL ring (320 B)
    ull hA[20], hB[20];
    ull hLA[20], hLB[20];   // local-memory staging (dynamic index u>>1)
#pragma unroll
    for (int j = 0; j < 20; j++) { hA[j] = 0ULL; hB[j] = 0ULL; }

    float xA = xA_ptr[0];
    float xB = xB_ptr[0];
    float hnAp = 0.0f, hnBp = 0.0f;

#pragma unroll 1
    for (int t = 0; t < T_; t++) {
        float xAn = 0.0f, xBn = 0.0f;
        if (t + 1 < T_) { xAn = xA_ptr[t + 1]; xBn = xB_ptr[t + 1]; }

        const ull xx2A = pk2(xA, xA);
        const ull xx2B = pk2(xB, xB);

        ull* cPtr = sC + tid;   // marches by BLK per unit

#pragma unroll 4
        for (int u = 0; u < H_; u++) {
            // accumulator init: (x*w_in + b, 0) via packed fma
            const ulonglong2 bp01 = *(const ulonglong2*)(sBP + u * 4);
            const ulonglong2 bp23 = *(const ulonglong2*)(sBP + u * 4 + 2);
            const ulonglong2 wp01 = *(const ulonglong2*)(sWP + u * 4);
            const ulonglong2 wp23 = *(const ulonglong2*)(sWP + u * 4 + 2);

            ull aAi = bp01.x, aAf = bp01.y, aAg = bp23.x, aAo = bp23.y;
            ull aBi = bp01.x, aBf = bp01.y, aBg = bp23.x, aBo = bp23.y;
            ffma2(aAi, wp01.x, xx2A); ffma2(aAf, wp01.y, xx2A);
            ffma2(aAg, wp23.x, xx2A); ffma2(aAo, wp23.y, xx2A);
            ffma2(aBi, wp01.x, xx2B); ffma2(aBf, wp01.y, xx2B);
            ffma2(aBg, wp23.x, xx2B); ffma2(aBo, wp23.y, xx2B);

            const ulonglong2* Wi = (const ulonglong2*)(sW + u * H_);
            const ulonglong2* Wf = (const ulonglong2*)(sW + (H_ + u) * H_);
            const ulonglong2* Wg = (const ulonglong2*)(sW + (2*H_ + u) * H_);
            const ulonglong2* Wo = (const ulonglong2*)(sW + (3*H_ + u) * H_);
#pragma unroll
            for (int c = 0; c < 10; c++) {
                ulonglong2 vi = Wi[c];
                ulonglong2 vf = Wf[c];
                ulonglong2 vg = Wg[c];
                ulonglong2 vo = Wo[c];
                ffma2(aAi, vi.x, hA[2*c]); ffma2(aAi, vi.y, hA[2*c+1]);
                ffma2(aBi, vi.x, hB[2*c]); ffma2(aBi, vi.y, hB[2*c+1]);
                ffma2(aAf, vf.x, hA[2*c]); ffma2(aAf, vf.y, hA[2*c+1]);
                ffma2(aBf, vf.x, hB[2*c]); ffma2(aBf, vf.y, hB[2*c+1]);
                ffma2(aAg, vg.x, hA[2*c]); ffma2(aAg, vg.y, hA[2*c+1]);
                ffma2(aBg, vg.x, hB[2*c]); ffma2(aBg, vg.y, hB[2*c+1]);
                ffma2(aAo, vo.x, hA[2*c]); ffma2(aAo, vo.y, hA[2*c+1]);
                ffma2(aBo, vo.x, hB[2*c]); ffma2(aBo, vo.y, hB[2*c+1]);
            }

            float lo, hi;
            upk2(lo, hi, aAi); const float vAi = lo + hi;
            upk2(lo, hi, aAf); const float vAf = lo + hi;
            upk2(lo, hi, aAg); const float vAg = lo + hi;
            upk2(lo, hi, aAo); const float vAo = lo + hi;
            upk2(lo, hi, aBi); const float vBi = lo + hi;
            upk2(lo, hi, aBf); const float vBf = lo + hi;
            upk2(lo, hi, aBg); const float vBg = lo + hi;
            upk2(lo, hi, aBo); const float vBo = lo + hi;

            const float iA = fsigm(vAi), fA = fsigm(vAf), gA = tanh_hw(vAg), oA = fsigm(vAo);
            const float iB = fsigm(vBi), fB = fsigm(vBf), gB = tanh_hw(vBg), oB = fsigm(vBo);

            float cA, cB;
            upk2(cA, cB, *cPtr);
            const float cnA = fmaf(fA, cA, iA * gA);
            const float cnB = fmaf(fB, cB, iB * gB);
            *cPtr = pk2(cnA, cnB);
            cPtr += BLK;
            const float hnA = oA * tanh_hw(cnA);
            const float hnB = oB * tanh_hw(cnB);

            if (u & 1) {
                hLA[u >> 1] = pk2(hnAp, hnA);
                hLB[u >> 1] = pk2(hnBp, hnB);
            } else {
                hnAp = hnA; hnBp = hnB;
            }
        }

        // commit h_new -> packed h regs (bulk local reload, MLP=20)
#pragma unroll
        for (int j = 0; j < 20; j++) {
            hA[j] = hLA[j];
            hB[j] = hLB[j];
        }
        xA = xAn; xB = xBn;
    }

    // FC head (packed dot products)
    float lgA[C_], lgB[C_];
#pragma unroll
    for (int cc = 0; cc < C_; cc++) {
        const ulonglong2* W = (const ulonglong2*)(sWfc + cc * H_);
        ull aA = 0ULL, aB = 0ULL;
#pragma unroll
        for (int c = 0; c < 10; c++) {
            ulonglong2 w = W[c];
            ffma2(aA, w.x, hA[2*c]); ffma2(aA, w.y, hA[2*c+1]);
            ffma2(aB, w.x, hB[2*c]); ffma2(aB, w.y, hB[2*c+1]);
        }
        float lo, hi;
        upk2(lo, hi, aA); lgA[cc] = sbfc[cc] + lo + hi;
        upk2(lo, hi, aB); lgB[cc] = sbfc[cc] + lo + hi;
    }

    int bestA = 0, bestB = 0;
    float bvA = lgA[0], bvB = lgB[0];
#pragma unroll
    for (int cc = 1; cc < C_; cc++) {
        if (lgA[cc] > bvA) { bvA = lgA[cc]; bestA = cc; }
        if (lgB[cc] > bvB) { bvB = lgB[cc]; bestB = cc; }
    }

    if (logit_off >= 0) {
        *(float4*)(out + logit_off + seqA * 4) = make_float4(lgA[0], lgA[1], lgA[2], lgA[3]);
        *(float4*)(out + logit_off + seqB * 4) = make_float4(lgB[0], lgB[1], lgB[2], lgB[3]);
    }
    if (arg_off >= 0) {
        out[arg_off + seqA] = (float)bestA;
        out[arg_off + seqB] = (float)bestB;
    }
}

extern "C" void kernel_launch(void* const* d_in, const int* in_sizes, int n_in,
                              void* d_out, int out_size)
{
    const float* x    = (const float*)d_in[0];
    const float* W_ih = (const float*)d_in[1];
    const float* W_hh = (const float*)d_in[2];
    const float* b_ih = (const float*)d_in[3];
    const float* b_hh = (const float*)d_in[4];
    const float* W_fc = (const float*)d_in[5];
    const float* b_fc = (const float*)d_in[6];
    float* out = (float*)d_out;

    const long long Btot = in_sizes[0] / T_;

    long long logit_off = 0, arg_off = 4LL * Btot;   // default: both
    if (out_size == (int)(Btot * 5)) {
        logit_off = 0; arg_off = 4LL * Btot;
    } else if (out_size == (int)(Btot * 4)) {
        logit_off = 0; arg_off = -1;
    } else if (out_size == (int)Btot) {
        logit_off = -1; arg_off = 0;
    }

    cudaFuncSetAttribute(lstm_fused_kernel,
                         cudaFuncAttributeMaxDynamicSharedMemorySize,
                         (int)SMEM_BYTES);

    const int grid = (int)((Btot + SPB - 1) / SPB);
    lstm_fused_kernel<<<grid, BLK, SMEM_BYTES>>>(
        x, W_ih, W_hh, b_ih, b_hh, W_fc, b_fc, out, logit_off, arg_off);
}

// round 15
// speedup vs baseline: 1.1093x; 1.0202x over previous
#include <cuda_runtime.h>
#include <cstdint>

// Problem constants
#define T_  40
#define H_  40
#define G_  160   // 4*H
#define C_  4
#define BLK 256
#define SPB 512   // sequences per block (2 per thread)

typedef unsigned long long ull;

// HW tanh (MUFU.TANH)
__device__ __forceinline__ float tanh_hw(float x) {
    float r; asm("tanh.approx.f32 %0, %1;" : "=f"(r) : "f"(x)); return r;
}
__device__ __forceinline__ float fsigm(float x) {
    return fmaf(0.5f, tanh_hw(0.5f * x), 0.5f);
}

// packed f32x2 helpers
__device__ __forceinline__ ull pk2(float lo, float hi) {
    ull r; asm("mov.b64 %0, {%1, %2};" : "=l"(r) : "f"(lo), "f"(hi)); return r;
}
__device__ __forceinline__ void upk2(float& lo, float& hi, ull v) {
    asm("mov.b64 {%0, %1}, %2;" : "=f"(lo), "=f"(hi) : "l"(v));
}
__device__ __forceinline__ void ffma2(ull& d, ull a, ull b) {
    asm("fma.rn.f32x2 %0, %1, %2, %0;" : "+l"(d) : "l"(a), "l"(b));
}

extern __shared__ float smem[];

// Shared layout (float offsets):
//   sW    [160*40] = 6400           @0
//   sWfc  [4*40]=160                @6400
//   sbfc  [8]                       @6560
//   -- 16B-aligned ull region @6568 (byte 26272) --
//   sWP  ull[160]  (w_in, 0) packed, index [u*4+gate]
//   sBP  ull[160]  (b, 0)   packed, index [u*4+gate]
//   sC   ull[40*256]  (cA,cB packed per unit per thread)
#define OFF_WFC 6400
#define OFF_BFC 6560
#define OFF_ULL 6568
#define N_C   (H_ * BLK)       // 10240 ull
#define SMEM_BYTES (OFF_ULL * 4 + (2 * G_ + N_C) * 8)   // 110752 B -> 2 CTAs/SM

__global__ __launch_bounds__(BLK, 2)
void lstm_fused_kernel(const float* __restrict__ x,
                       const float* __restrict__ W_ih,
                       const float* __restrict__ W_hh,
                       const float* __restrict__ b_ih,
                       const float* __restrict__ b_hh,
                       const float* __restrict__ W_fc,
                       const float* __restrict__ b_fc,
                       float* __restrict__ out,
                       long long logit_off,
                       long long arg_off)
{
    float* sW   = smem;
    float* sWfc = smem + OFF_WFC;
    float* sbfc = smem + OFF_BFC;
    ull*   sWP  = (ull*)(smem + OFF_ULL);
    ull*   sBP  = sWP + G_;
    ull*   sC   = sBP + G_;

    const int tid = threadIdx.x;

    // Stage weights
    for (int i = tid; i < G_ * H_; i += BLK) sW[i] = W_hh[i];
    for (int i = tid; i < G_; i += BLK) {
        const int g = i / H_, u = i % H_;
        sWP[u * 4 + g] = pk2(W_ih[i], 0.0f);
        sBP[u * 4 + g] = pk2(b_ih[i] + b_hh[i], 0.0f);
    }
    for (int i = tid; i < C_ * H_; i += BLK) sWfc[i] = W_fc[i];
    if (tid < C_) sbfc[tid] = b_fc[tid];
    for (int i = tid; i < N_C; i += BLK) sC[i] = 0ULL;
    __syncthreads();

    const long long seqA = (long long)blockIdx.x * SPB + tid;
    const long long seqB = seqA + BLK;
    const float* xA_ptr = x + seqA * T_;
    const float* xB_ptr = x + seqB * T_;

    // h pairs in registers; h_new staged via per-thread LOCAL ring (320 B)
    ull hA[20], hB[20];
    ull hLA[20], hLB[20];   // local-memory staging (dynamic index u>>1)
#pragma unroll
    for (int j = 0; j < 20; j++) { hA[j] = 0ULL; hB[j] = 0ULL; }

    float xA = xA_ptr[0];
    float xB = xB_ptr[0];
    float hnAp = 0.0f, hnBp = 0.0f;

#pragma unroll 1
    for (int t = 0; t < T_; t++) {
        float xAn = 0.0f, xBn = 0.0f;
        if (t + 1 < T_) { xAn = xA_ptr[t + 1]; xBn = xB_ptr[t + 1]; }

        const ull xx2A = pk2(xA, xA);
        const ull xx2B = pk2(xB, xB);

        ull* cPtr = sC + tid;   // marches by BLK per unit

#pragma unroll 2
        for (int u = 0; u < H_; u++) {
            // accumulator init: (x*w_in + b, 0) via packed fma
            const ulonglong2 bp01 = *(const ulonglong2*)(sBP + u * 4);
            const ulonglong2 bp23 = *(const ulonglong2*)(sBP + u * 4 + 2);
            const ulonglong2 wp01 = *(const ulonglong2*)(sWP + u * 4);
            const ulonglong2 wp23 = *(const ulonglong2*)(sWP + u * 4 + 2);

            ull aAi = bp01.x, aAf = bp01.y, aAg = bp23.x, aAo = bp23.y;
            ull aBi = bp01.x, aBf = bp01.y, aBg = bp23.x, aBo = bp23.y;
            ffma2(aAi, wp01.x, xx2A); ffma2(aAf, wp01.y, xx2A);
            ffma2(aAg, wp23.x, xx2A); ffma2(aAo, wp23.y, xx2A);
            ffma2(aBi, wp01.x, xx2B); ffma2(aBf, wp01.y, xx2B);
            ffma2(aBg, wp23.x, xx2B); ffma2(aBo, wp23.y, xx2B);

            const ulonglong2* Wi = (const ulonglong2*)(sW + u * H_);
            const ulonglong2* Wf = (const ulonglong2*)(sW + (H_ + u) * H_);
            const ulonglong2* Wg = (const ulonglong2*)(sW + (2*H_ + u) * H_);
            const ulonglong2* Wo = (const ulonglong2*)(sW + (3*H_ + u) * H_);
#pragma unroll
            for (int c = 0; c < 10; c++) {
                ulonglong2 vi = Wi[c];
                ulonglong2 vf = Wf[c];
                ulonglong2 vg = Wg[c];
                ulonglong2 vo = Wo[c];
                ffma2(aAi, vi.x, hA[2*c]); ffma2(aAi, vi.y, hA[2*c+1]);
                ffma2(aBi, vi.x, hB[2*c]); ffma2(aBi, vi.y, hB[2*c+1]);
                ffma2(aAf, vf.x, hA[2*c]); ffma2(aAf, vf.y, hA[2*c+1]);
                ffma2(aBf, vf.x, hB[2*c]); ffma2(aBf, vf.y, hB[2*c+1]);
                ffma2(aAg, vg.x, hA[2*c]); ffma2(aAg, vg.y, hA[2*c+1]);
                ffma2(aBg, vg.x, hB[2*c]); ffma2(aBg, vg.y, hB[2*c+1]);
                ffma2(aAo, vo.x, hA[2*c]); ffma2(aAo, vo.y, hA[2*c+1]);
                ffma2(aBo, vo.x, hB[2*c]); ffma2(aBo, vo.y, hB[2*c+1]);
            }

            float lo, hi;
            upk2(lo, hi, aAi); const float vAi = lo + hi;
            upk2(lo, hi, aAf); const float vAf = lo + hi;
            upk2(lo, hi, aAg); const float vAg = lo + hi;
            upk2(lo, hi, aAo); const float vAo = lo + hi;
            upk2(lo, hi, aBi); const float vBi = lo + hi;
            upk2(lo, hi, aBf); const float vBf = lo + hi;
            upk2(lo, hi, aBg); const float vBg = lo + hi;
            upk2(lo, hi, aBo); const float vBo = lo + hi;

            const float iA = fsigm(vAi), fA = fsigm(vAf), gA = tanh_hw(vAg), oA = fsigm(vAo);
            const float iB = fsigm(vBi), fB = fsigm(vBf), gB = tanh_hw(vBg), oB = fsigm(vBo);

            float cA, cB;
            upk2(cA, cB, *cPtr);
            const float cnA = fmaf(fA, cA, iA * gA);
            const float cnB = fmaf(fB, cB, iB * gB);
            *cPtr = pk2(cnA, cnB);
            cPtr += BLK;
            const float hnA = oA * tanh_hw(cnA);
            const float hnB = oB * tanh_hw(cnB);

            if (u & 1) {
                hLA[u >> 1] = pk2(hnAp, hnA);
                hLB[u >> 1] = pk2(hnBp, hnB);
            } else {
                hnAp = hnA; hnBp = hnB;
            }
        }

        // commit h_new -> packed h regs (bulk local reload, MLP=20)
#pragma unroll
        for (int j = 0; j < 20; j++) {
            hA[j] = hLA[j];
            hB[j] = hLB[j];
        }
        xA = xAn; xB = xBn;
    }

    // FC head (packed dot products)
    float lgA[C_], lgB[C_];
#pragma unroll
    for (int cc = 0; cc < C_; cc++) {
        const ulonglong2* W = (const ulonglong2*)(sWfc + cc * H_);
        ull aA = 0ULL, aB = 0ULL;
#pragma unroll
        for (int c = 0; c < 10; c++) {
            ulonglong2 w = W[c];
            ffma2(aA, w.x, hA[2*c]); ffma2(aA, w.y, hA[2*c+1]);
            ffma2(aB, w.x, hB[2*c]); ffma2(aB, w.y, hB[2*c+1]);
        }
        float lo, hi;
        upk2(lo, hi, aA); lgA[cc] = sbfc[cc] + lo + hi;
        upk2(lo, hi, aB); lgB[cc] = sbfc[cc] + lo + hi;
    }

    int bestA = 0, bestB = 0;
    float bvA = lgA[0], bvB = lgB[0];
#pragma unroll
    for (int cc = 1; cc < C_; cc++) {
        if (lgA[cc] > bvA) { bvA = lgA[cc]; bestA = cc; }
        if (lgB[cc] > bvB) { bvB = lgB[cc]; bestB = cc; }
    }

    if (logit_off >= 0) {
        *(float4*)(out + logit_off + seqA * 4) = make_float4(lgA[0], lgA[1], lgA[2], lgA[3]);
        *(float4*)(out + logit_off + seqB * 4) = make_float4(lgB[0], lgB[1], lgB[2], lgB[3]);
    }
    if (arg_off >= 0) {
        out[arg_off + seqA] = (float)bestA;
        out[arg_off + seqB] = (float)bestB;
    }
}

extern "C" void kernel_launch(void* const* d_in, const int* in_sizes, int n_in,
                              void* d_out, int out_size)
{
    const float* x    = (const float*)d_in[0];
    const float* W_ih = (const float*)d_in[1];
    const float* W_hh = (const float*)d_in[2];
    const float* b_ih = (const float*)d_in[3];
    const float* b_hh = (const float*)d_in[4];
    const float* W_fc = (const float*)d_in[5];
    const float* b_fc = (const float*)d_in[6];
    float* out = (float*)d_out;

    const long long Btot = in_sizes[0] / T_;

    long long logit_off = 0, arg_off = 4LL * Btot;   // default: both
    if (out_size == (int)(Btot * 5)) {
        logit_off = 0; arg_off = 4LL * Btot;
    } else if (out_size == (int)(Btot * 4)) {
        logit_off = 0; arg_off = -1;
    } else if (out_size == (int)Btot) {
        logit_off = -1; arg_off = 0;
    }

    cudaFuncSetAttribute(lstm_fused_kernel,
                         cudaFuncAttributeMaxDynamicSharedMemorySize,
                         (int)SMEM_BYTES);

    const int grid = (int)((Btot + SPB - 1) / SPB);
    lstm_fused_kernel<<<grid, BLK, SMEM_BYTES>>>(
        x, W_ih, W_hh, b_ih, b_hh, W_fc, b_fc, out, logit_off, arg_off);
}

// round 16
// speedup vs baseline: 1.7931x; 1.6165x over previous
#include <cuda_runtime.h>
#include <cstdint>

// Problem constants
#define T_  40
#define H_  40
#define G_  160   // 4*H
#define C_  4
#define BLK 128          // 4 warps
#define SPW 16           // sequences (M rows) per warp
#define SPB 64           // sequences per CTA

// HW tanh (MUFU.TANH)
__device__ __forceinline__ float tanh_hw(float x) {
    float r; asm("tanh.approx.f32 %0, %1;" : "=f"(r) : "f"(x)); return r;
}
__device__ __forceinline__ float fsigm(float x) {
    return fmaf(0.5f, tanh_hw(0.5f * x), 0.5f);
}
// tf32 round (keeps value in f32 register, low mantissa zeroed/rounded)
__device__ __forceinline__ uint32_t tf32_of(float x) {
    uint32_t r; asm("cvt.rna.tf32.f32 %0, %1;" : "=r"(r) : "f"(x)); return r;
}

__device__ __forceinline__ void mma_tf32(float& d0, float& d1, float& d2, float& d3,
                                         uint32_t a0, uint32_t a1, uint32_t a2, uint32_t a3,
                                         uint32_t b0, uint32_t b1) {
    asm volatile(
        "mma.sync.aligned.m16n8k8.row.col.f32.tf32.tf32.f32 "
        "{%0,%1,%2,%3}, {%4,%5,%6,%7}, {%8,%9}, {%0,%1,%2,%3};"
        : "+f"(d0), "+f"(d1), "+f"(d2), "+f"(d3)
        : "r"(a0), "r"(a1), "r"(a2), "r"(a3), "r"(b0), "r"(b1));
}

extern __shared__ float smem[];

// Shared layout (float offsets):
//   sBhi [40][168]  = 6720   @0       B[k][n] = tf32_hi(W_hh[n][k]); bank = 8k+n
//   sBlo [40][168]  = 6720   @6720
//   sHT  [40][72]   = 2880   @13440   h transposed [k][row]; bank = 8k+row
//   sWin [160]               @16320   (8B aligned)
//   sBia [160]               @16480
#define OFF_BLO 6720
#define OFF_HT  13440
#define OFF_WIN 16320
#define OFF_BIA 16480
#define SMEM_FLOATS 16640
#define SMEM_BYTES (SMEM_FLOATS * 4)   // 66560 B -> 3 CTAs/SM

__global__ __launch_bounds__(BLK, 3)
void lstm_mma_kernel(const float* __restrict__ x,
                     const float* __restrict__ W_ih,
                     const float* __restrict__ W_hh,
                     const float* __restrict__ b_ih,
                     const float* __restrict__ b_hh,
                     const float* __restrict__ W_fc,
                     const float* __restrict__ b_fc,
                     float* __restrict__ out,
                     long long logit_off,
                     long long arg_off)
{
    float* sBhi = smem;
    float* sBlo = smem + OFF_BLO;
    float* sHT  = smem + OFF_HT;
    float* sWin = smem + OFF_WIN;
    float* sBia = smem + OFF_BIA;

    const int tid  = threadIdx.x;
    const int wid  = tid >> 5;
    const int lane = tid & 31;
    const int g    = lane >> 2;   // groupID (row within m16 / n within n8)
    const int t    = lane & 3;    // threadID in group (k index)

    // ---- stage weights (tf32 hi/lo split for W_hh) ----
    for (int i = tid; i < G_ * H_; i += BLK) {
        const int n = i / H_, k = i % H_;
        float w = W_hh[i];
        uint32_t hiu = tf32_of(w);
        float hif = __uint_as_float(hiu);
        uint32_t lou = tf32_of(w - hif);
        sBhi[k * 168 + n] = hif;
        sBlo[k * 168 + n] = __uint_as_float(lou);
    }
    for (int i = tid; i < G_; i += BLK) {
        sWin[i] = W_ih[i];
        sBia[i] = b_ih[i] + b_hh[i];
    }
    for (int i = tid; i < H_ * 72; i += BLK) sHT[i] = 0.0f;
    __syncthreads();

    const int rowA = wid * SPW + g;          // this lane's lower row (local seq)
    const int baseA = t * 72 + rowA;          // sHT index for (k=t, row=rowA)
    const int baseB = t * 168 + g;            // sB index for (k=t, n=g)

    const long long seq0 = (long long)blockIdx.x * SPB + rowA;      // lower row seq
    const float* xp0 = x + seq0 * T_;
    const float* xp1 = xp0 + 8LL * T_;                               // row+8 seq

    float cReg[20];                            // c fragments: 5 groups x 4 positions
#pragma unroll
    for (int j = 0; j < 20; j++) cReg[j] = 0.0f;

#pragma unroll 1
    for (int ts = 0; ts < T_; ts++) {
        const float xa = __ldg(xp0 + ts);
        const float xb = __ldg(xp1 + ts);

        // ---- load A fragments (h from sHT), split hi/lo ----
        uint32_t Ahi[5][4], Alo[5][4];
#pragma unroll
        for (int kc = 0; kc < 5; kc++) {
#pragma unroll
            for (int j = 0; j < 4; j++) {
                const int idx = baseA + kc * 576 + ((j >> 1) ? 288 : 0) + ((j & 1) ? 8 : 0);
                float v = sHT[idx];
                uint32_t hiu = tf32_of(v);
                float hif = __uint_as_float(hiu);
                Ahi[kc][j] = hiu;
                Alo[kc][j] = tf32_of(v - hif);
            }
        }

        // ---- 5 unit groups ----
#pragma unroll
        for (int U = 0; U < 5; U++) {
            float pre[4][4];
#pragma unroll
            for (int gate = 0; gate < 4; gate++) {
                float d0 = 0.0f, d1 = 0.0f, d2 = 0.0f, d3 = 0.0f;
                const int nb = gate * 40 + 8 * U;
#pragma unroll
                for (int kc = 0; kc < 5; kc++) {
                    const int ib = baseB + kc * 1344 + nb;
                    uint32_t bh0 = __float_as_uint(sBhi[ib]);
                    uint32_t bh1 = __float_as_uint(sBhi[ib + 672]);
                    uint32_t bl0 = __float_as_uint(sBlo[ib]);
                    uint32_t bl1 = __float_as_uint(sBlo[ib + 672]);
                    mma_tf32(d0, d1, d2, d3,
                             Ahi[kc][0], Ahi[kc][1], Ahi[kc][2], Ahi[kc][3], bh0, bh1);
                    mma_tf32(d0, d1, d2, d3,
                             Ahi[kc][0], Ahi[kc][1], Ahi[kc][2], Ahi[kc][3], bl0, bl1);
                    mma_tf32(d0, d1, d2, d3,
                             Alo[kc][0], Alo[kc][1], Alo[kc][2], Alo[kc][3], bh0, bh1);
                }
                const int wi = gate * 40 + 8 * U + 2 * t;
                const float2 wv = *(const float2*)(sWin + wi);
                const float2 bv = *(const float2*)(sBia + wi);
                pre[gate][0] = d0 + xa * wv.x + bv.x;
                pre[gate][1] = d1 + xa * wv.y + bv.y;
                pre[gate][2] = d2 + xb * wv.x + bv.x;
                pre[gate][3] = d3 + xb * wv.y + bv.y;
            }
            // activations + cell update + store h_new
#pragma unroll
            for (int p = 0; p < 4; p++) {
                const float ig = fsigm(pre[0][p]);
                const float fg = fsigm(pre[1][p]);
                const float gg = tanh_hw(pre[2][p]);
                const float og = fsigm(pre[3][p]);
                const float cn = fmaf(fg, cReg[U * 4 + p], ig * gg);
                cReg[U * 4 + p] = cn;
                const float hn = og * tanh_hw(cn);
                const int u = 8 * U + 2 * t + (p & 1);
                const int r = rowA + ((p >> 1) ? 8 : 0);
                sHT[u * 72 + r] = hn;
            }
        }
        __syncwarp();   // make this warp's h_T stores visible to its own A loads
    }

    // ---- FC head + argmax ----
    __syncthreads();
    if (tid < SPB) {
        float h[H_];
#pragma unroll
        for (int u = 0; u < H_; u++) h[u] = sHT[u * 72 + tid];

        float lg[C_];
#pragma unroll
        for (int cc = 0; cc < C_; cc++) {
            float a = __ldg(b_fc + cc);
#pragma unroll
            for (int u = 0; u < H_; u++)
                a = fmaf(__ldg(W_fc + cc * H_ + u), h[u], a);
            lg[cc] = a;
        }
        int best = 0;
        float bv = lg[0];
#pragma unroll
        for (int cc = 1; cc < C_; cc++)
            if (lg[cc] > bv) { bv = lg[cc]; best = cc; }

        const long long seq = (long long)blockIdx.x * SPB + tid;
        if (logit_off >= 0)
            *(float4*)(out + logit_off + seq * 4) = make_float4(lg[0], lg[1], lg[2], lg[3]);
        if (arg_off >= 0)
            out[arg_off + seq] = (float)best;
    }
}

extern "C" void kernel_launch(void* const* d_in, const int* in_sizes, int n_in,
                              void* d_out, int out_size)
{
    const float* x    = (const float*)d_in[0];
    const float* W_ih = (const float*)d_in[1];
    const float* W_hh = (const float*)d_in[2];
    const float* b_ih = (const float*)d_in[3];
    const float* b_hh = (const float*)d_in[4];
    const float* W_fc = (const float*)d_in[5];
    const float* b_fc = (const float*)d_in[6];
    float* out = (float*)d_out;

    const long long Btot = in_sizes[0] / T_;

    long long logit_off = 0, arg_off = 4LL * Btot;   // default: both
    if (out_size == (int)(Btot * 5)) {
        logit_off = 0; arg_off = 4LL * Btot;
    } else if (out_size == (int)(Btot * 4)) {
        logit_off = 0; arg_off = -1;
    } else if (out_size == (int)Btot) {
        logit_off = -1; arg_off = 0;
    }

    cudaFuncSetAttribute(lstm_mma_kernel,
                         cudaFuncAttributeMaxDynamicSharedMemorySize,
                         (int)SMEM_BYTES);

    const int grid = (int)((Btot + SPB - 1) / SPB);
    lstm_mma_kernel<<<grid, BLK, SMEM_BYTES>>>(
        x, W_ih, W_hh, b_ih, b_hh, W_fc, b_fc, out, logit_off, arg_off);
}